// round 15
// baseline (speedup 1.0000x reference)
#include <cuda_runtime.h>
#include <cuda_fp16.h>
#include <mma.h>
#include <math.h>
#include <stdint.h>

using namespace nvcuda;

// Problem constants
#define BATCH 4
#define TT 2048
#define EE 1024
#define HH 16
#define DD 64
#define SEG 512
#define E3 3072

// Scratch (device globals: allocation-free)
static __device__ __half g_qkvh[(size_t)BATCH * TT * E3];
static __device__ __half g_yh[(size_t)BATCH * TT * EE];
static __device__ __half g_xh[(size_t)BATCH * TT * EE];
static __device__ __half g_wqh[(size_t)EE * E3];
static __device__ __half g_wph[(size_t)EE * EE];

// ---------------------------------------------------------------------------
// helpers
// ---------------------------------------------------------------------------
__device__ __forceinline__ void cp_async16(uint32_t smem_dst, const void* gsrc) {
    asm volatile("cp.async.cg.shared.global [%0], [%1], 16;\n" :: "r"(smem_dst), "l"(gsrc));
}
__device__ __forceinline__ void cp_commit() {
    asm volatile("cp.async.commit_group;\n" ::: "memory");
}
template <int N>
__device__ __forceinline__ void cp_wait() {
    asm volatile("cp.async.wait_group %0;\n" :: "n"(N) : "memory");
}
__device__ __forceinline__ void ldsm_x4(
    uint32_t& r0, uint32_t& r1, uint32_t& r2, uint32_t& r3, uint32_t addr)
{
    asm volatile("ldmatrix.sync.aligned.m8n8.x4.shared.b16 {%0,%1,%2,%3}, [%4];"
        : "=r"(r0), "=r"(r1), "=r"(r2), "=r"(r3) : "r"(addr));
}
__device__ __forceinline__ void ldsm_x4_trans(
    uint32_t& r0, uint32_t& r1, uint32_t& r2, uint32_t& r3, uint32_t addr)
{
    asm volatile("ldmatrix.sync.aligned.m8n8.x4.trans.shared.b16 {%0,%1,%2,%3}, [%4];"
        : "=r"(r0), "=r"(r1), "=r"(r2), "=r"(r3) : "r"(addr));
}
__device__ __forceinline__ float ex2f(float x) {
    float r;
    asm("ex2.approx.ftz.f32 %0, %1;" : "=f"(r) : "f"(x));
    return r;
}

// Fused fp32 -> fp16 conversion of x, W_qkv, W_proj in ONE launch.
__global__ __launch_bounds__(256) void cvt_all_kernel(
    const float* __restrict__ x,  __half* __restrict__ xh,  int n4x,
    const float* __restrict__ wq, __half* __restrict__ wqh, int n4q,
    const float* __restrict__ wp, __half* __restrict__ wph, int n4p)
{
    int i = blockIdx.x * 256 + threadIdx.x;
    const float* src; __half* dst; int off;
    if (i < n4x)                  { src = x;  dst = xh;  off = i; }
    else if (i < n4x + n4q)       { src = wq; dst = wqh; off = i - n4x; }
    else if (i < n4x + n4q + n4p) { src = wp; dst = wph; off = i - n4x - n4q; }
    else return;
    float4 v = ((const float4*)src)[off];
    ((__half2*)dst)[off * 2]     = __floats2half2_rn(v.x, v.y);
    ((__half2*)dst)[off * 2 + 1] = __floats2half2_rn(v.z, v.w);
}

// ---------------------------------------------------------------------------
// FP16 GEMM (exact R13/R14 passing config): C = A @ B + bias. 128x128 tile,
// BK=32, 4-stage cp.async ring, 4 warps (2x2), warp tile 64x64.
// ---------------------------------------------------------------------------
#define GLDA 40
#define GLDB 136
#define A_H (128 * GLDA)
#define B_H (32 * GLDB)
#define STAGE_H (A_H + B_H)
#define GSMEM_BYTES (4 * STAGE_H * 2)

template <typename OutT>
__global__ __launch_bounds__(128, 2) void gemm_f16(
    const __half* __restrict__ A, const __half* __restrict__ B,
    const float* __restrict__ bias, OutT* __restrict__ C,
    int M, int N, int K)
{
    extern __shared__ __half smemh[];
    const uint32_t smem_base = (uint32_t)__cvta_generic_to_shared(smemh);

    const int tid = threadIdx.x;
    const int wid = tid >> 5;
    const int wm = wid >> 1;
    const int wn = wid & 1;
    const int row0 = blockIdx.y * 128;
    const int col0 = blockIdx.x * 128;

    const int nsteps = K >> 5;

    auto stage_load = [&](int s, int k0) {
        uint32_t sa = smem_base + (uint32_t)(s * STAGE_H) * 2u;
        uint32_t sb = sa + (uint32_t)A_H * 2u;
        #pragma unroll
        for (int i = 0; i < 4; i++) {
            int c = tid + i * 128;
            int r = c >> 2, c8 = c & 3;
            cp_async16(sa + (uint32_t)(r * GLDA + c8 * 8) * 2u,
                       &A[(size_t)(row0 + r) * K + k0 + c8 * 8]);
        }
        #pragma unroll
        for (int i = 0; i < 4; i++) {
            int c = tid + i * 128;
            int r = c >> 4, c8 = c & 15;
            cp_async16(sb + (uint32_t)(r * GLDB + c8 * 8) * 2u,
                       &B[(size_t)(k0 + r) * N + col0 + c8 * 8]);
        }
    };

    wmma::fragment<wmma::accumulator, 16, 16, 16, float> acc[4][4];
    #pragma unroll
    for (int i = 0; i < 4; i++)
        #pragma unroll
        for (int j = 0; j < 4; j++)
            wmma::fill_fragment(acc[i][j], 0.0f);

    stage_load(0, 0);  cp_commit();
    stage_load(1, 32); cp_commit();
    stage_load(2, 64); cp_commit();

    for (int step = 0; step < nsteps; step++) {
        cp_wait<2>();
        __syncthreads();

        if (step + 3 < nsteps) stage_load((step + 3) & 3, (step + 3) * 32);
        cp_commit();

        const __half* sA = smemh + (step & 3) * STAGE_H;
        const __half* sB = sA + A_H;

        #pragma unroll
        for (int ks = 0; ks < 2; ks++) {
            wmma::fragment<wmma::matrix_a, 16, 16, 16, __half, wmma::row_major> af[4];
            wmma::fragment<wmma::matrix_b, 16, 16, 16, __half, wmma::row_major> bf[4];
            #pragma unroll
            for (int i = 0; i < 4; i++)
                wmma::load_matrix_sync(af[i], &sA[(wm * 64 + 16 * i) * GLDA + ks * 16], GLDA);
            #pragma unroll
            for (int j = 0; j < 4; j++)
                wmma::load_matrix_sync(bf[j], &sB[(ks * 16) * GLDB + wn * 64 + 16 * j], GLDB);
            #pragma unroll
            for (int i = 0; i < 4; i++)
                #pragma unroll
                for (int j = 0; j < 4; j++)
                    wmma::mma_sync(acc[i][j], af[i], bf[j], acc[i][j]);
        }
    }

    __syncthreads();

    // Epilogue via fp32 smem overlay
    float* sC = (float*)smemh;
    #pragma unroll
    for (int i = 0; i < 4; i++)
        #pragma unroll
        for (int j = 0; j < 4; j++)
            wmma::store_matrix_sync(&sC[(wm * 64 + 16 * i) * 132 + wn * 64 + 16 * j],
                                    acc[i][j], 132, wmma::mem_row_major);
    __syncthreads();

    #pragma unroll
    for (int idx = tid; idx < 4096; idx += 128) {
        int r = idx >> 5, c4 = idx & 31;
        float4 v = *(float4*)&sC[r * 132 + c4 * 4];
        float4 bv = *(const float4*)&bias[col0 + c4 * 4];
        v.x += bv.x; v.y += bv.y; v.z += bv.z; v.w += bv.w;
        if (sizeof(OutT) == 2) {
            __half2* dst = (__half2*)&C[(size_t)(row0 + r) * N + col0 + c4 * 4];
            dst[0] = __floats2half2_rn(v.x, v.y);
            dst[1] = __floats2half2_rn(v.z, v.w);
        } else {
            *(float4*)&((float*)C)[(size_t)(row0 + r) * N + col0 + c4 * 4] = v;
        }
    }
}

// ---------------------------------------------------------------------------
// Flash attention, m16n8k16.f16 (fp32 acc). Br=128, 8 warps.
// KV ring of THREE 128-key tiles; each tile processed as TWO 64-key halves
// with register reuse (one cp_wait + one barrier per 128 keys).
// Register-resident P; max-free softmax; scale*log2e folded into Q (bare ex2).
// K b-frags via ldmatrix.x4; V^T via ldmatrix.x4.trans.
// ---------------------------------------------------------------------------
#define LDH 72
#define KV_TILE (128 * LDH)                           // halves per 128-key tile
#define ASMEM_BYTES ((6 * KV_TILE + 128 * LDH) * 2)   // 129024 B

__device__ __forceinline__ void mma_f16_16x8x16(
    float c[4], const uint32_t a[4], const uint32_t b0, const uint32_t b1)
{
    asm volatile(
        "mma.sync.aligned.m16n8k16.row.col.f32.f16.f16.f32 "
        "{%0,%1,%2,%3}, {%4,%5,%6,%7}, {%8,%9}, {%0,%1,%2,%3};"
        : "+f"(c[0]), "+f"(c[1]), "+f"(c[2]), "+f"(c[3])
        : "r"(a[0]), "r"(a[1]), "r"(a[2]), "r"(a[3]), "r"(b0), "r"(b1));
}

__global__ __launch_bounds__(256) void attn_f16(
    const __half* __restrict__ qkv, __half* __restrict__ y)
{
    extern __shared__ __half smemh[];
    __half* sP = smemh + 6 * KV_TILE;   // Q staging only
    const uint32_t smem_u = (uint32_t)__cvta_generic_to_shared(smemh);
    const uint32_t sP_u = smem_u + (uint32_t)(6 * KV_TILE) * 2u;

    const int tid = threadIdx.x;
    const int w = tid >> 5;
    const int lane = tid & 31;
    const int g = lane >> 2;
    const int t = lane & 3;

    const int qt = (int)gridDim.x - 1 - (int)blockIdx.x;
    const int q0 = qt * 128;
    const int bh = blockIdx.y;
    const int b = bh / HH;
    const int h = bh % HH;

    const __half* base = qkv + (size_t)b * TT * E3 + h * DD;

    const bool causal = (q0 >= SEG);
    const int kv_end = causal ? (q0 + 128) : SEG;
    const int ntiles = kv_end >> 7;   // 128-key tiles; kv_end always mult of 128

    auto prefetch = [&](int tile) {
        const int s = tile % 3;
        uint32_t k_u = smem_u + (uint32_t)(s * KV_TILE) * 2u;
        uint32_t v_u = smem_u + (uint32_t)((3 + s) * KV_TILE) * 2u;
        const int kc0 = tile * 128;
        #pragma unroll
        for (int i = 0; i < 4; i++) {
            int idx = tid + i * 256;
            int r = idx >> 3, c8 = idx & 7;     // r 0..127
            const __half* gp = &base[(size_t)(kc0 + r) * E3 + c8 * 8];
            uint32_t soff = (uint32_t)(r * LDH + c8 * 8) * 2u;
            cp_async16(k_u + soff, gp + EE);
            cp_async16(v_u + soff, gp + 2 * EE);
        }
    };

    #pragma unroll
    for (int i = 0; i < 4; i++) {
        int idx = tid + i * 256;
        int r = idx >> 3, c8 = idx & 7;
        cp_async16(sP_u + (uint32_t)(r * LDH + c8 * 8) * 2u,
                   &base[(size_t)(q0 + r) * E3 + c8 * 8]);
    }
    cp_commit();
    prefetch(0); cp_commit();
    prefetch(1); cp_commit();

    cp_wait<2>();
    __syncthreads();

    // Q a-frags, pre-scaled by scale*log2e = 0.18033688
    uint32_t aQ[4][4];
    {
        const int r0 = w * 16 + g;
        const __half2 qs = __float2half2_rn(0.18033688f);
        #pragma unroll
        for (int ks = 0; ks < 4; ks++) {
            __half2 v0 = *(const __half2*)&sP[r0 * LDH + ks * 16 + 2 * t];
            __half2 v1 = *(const __half2*)&sP[(r0 + 8) * LDH + ks * 16 + 2 * t];
            __half2 v2 = *(const __half2*)&sP[r0 * LDH + ks * 16 + 2 * t + 8];
            __half2 v3 = *(const __half2*)&sP[(r0 + 8) * LDH + ks * 16 + 2 * t + 8];
            v0 = __hmul2(v0, qs); v1 = __hmul2(v1, qs);
            v2 = __hmul2(v2, qs); v3 = __hmul2(v3, qs);
            aQ[ks][0] = *(uint32_t*)&v0;
            aQ[ks][1] = *(uint32_t*)&v1;
            aQ[ks][2] = *(uint32_t*)&v2;
            aQ[ks][3] = *(uint32_t*)&v3;
        }
    }

    float O[8][4];
    #pragma unroll
    for (int j = 0; j < 8; j++) { O[j][0] = O[j][1] = O[j][2] = O[j][3] = 0.0f; }
    float l0 = 0.0f, l1 = 0.0f;

    const int row0g = q0 + w * 16 + g;
    const int rowmax = q0 + w * 16 + 15;

    const int k_row_off = (lane & 7) + 8 * ((lane >> 4) & 1);
    const int k_col_off = ((lane >> 3) & 1) * 8;

    for (int tile = 0; tile < ntiles; tile++) {
        const int s = tile % 3;

        cp_wait<1>();
        __syncthreads();

        if (tile + 2 < ntiles) prefetch(tile + 2);
        cp_commit();

        const uint32_t sK_u = smem_u + (uint32_t)(s * KV_TILE) * 2u;
        const uint32_t sV_u = smem_u + (uint32_t)((3 + s) * KV_TILE) * 2u;

        #pragma unroll
        for (int half = 0; half < 2; half++) {
            const int kc0 = tile * 128 + half * 64;
            if (causal && kc0 > rowmax) break;   // half1 (and beyond) masked out

            const uint32_t kB = sK_u + (uint32_t)(half * 64 * LDH) * 2u;
            const uint32_t vB = sV_u + (uint32_t)(half * 64 * LDH) * 2u;

            // ---- S = (log2e*scale*Q) @ K^T ----
            float sacc[8][4];
            #pragma unroll
            for (int j = 0; j < 8; j++)
                sacc[j][0] = sacc[j][1] = sacc[j][2] = sacc[j][3] = 0.0f;
            #pragma unroll
            for (int ks = 0; ks < 4; ks++) {
                #pragma unroll
                for (int jp = 0; jp < 4; jp++) {
                    const int j = jp * 2;
                    uint32_t b0, b1, b2, b3;
                    uint32_t addr = kB +
                        (uint32_t)((j * 8 + k_row_off) * LDH + ks * 16 + k_col_off) * 2u;
                    ldsm_x4(b0, b1, b2, b3, addr);
                    mma_f16_16x8x16(sacc[j],     aQ[ks], b0, b1);
                    mma_f16_16x8x16(sacc[j + 1], aQ[ks], b2, b3);
                }
            }

            // ---- bare ex2 + pack P into a-frags ----
            const bool maskT = causal && (kc0 + 63 > q0 + w * 16);
            uint32_t aP[4][4];
            float sum0 = 0.0f, sum1 = 0.0f;
            #pragma unroll
            for (int j = 0; j < 8; j++) {
                float v0 = sacc[j][0];
                float v1 = sacc[j][1];
                float v2 = sacc[j][2];
                float v3 = sacc[j][3];
                if (maskT) {
                    int c = kc0 + j * 8 + 2 * t;
                    int r0m = row0g, r1m = row0g + 8;
                    if (c     > r0m) v0 = -1e30f;
                    if (c + 1 > r0m) v1 = -1e30f;
                    if (c     > r1m) v2 = -1e30f;
                    if (c + 1 > r1m) v3 = -1e30f;
                }
                float p0 = ex2f(v0);
                float p1 = ex2f(v1);
                float p2 = ex2f(v2);
                float p3 = ex2f(v3);
                sum0 += p0 + p1;
                sum1 += p2 + p3;
                __half2 h01 = __floats2half2_rn(p0, p1);
                __half2 h23 = __floats2half2_rn(p2, p3);
                const int ks = j >> 1;
                if ((j & 1) == 0) {
                    aP[ks][0] = *(uint32_t*)&h01;
                    aP[ks][1] = *(uint32_t*)&h23;
                } else {
                    aP[ks][2] = *(uint32_t*)&h01;
                    aP[ks][3] = *(uint32_t*)&h23;
                }
            }
            l0 += sum0;
            l1 += sum1;

            // ---- O += P @ V : V^T frags via ldmatrix.x4.trans ----
            #pragma unroll
            for (int ks = 0; ks < 4; ks++) {
                #pragma unroll
                for (int jj = 0; jj < 4; jj++) {
                    uint32_t r0, r1, r2, r3;
                    uint32_t addr = vB +
                        (uint32_t)(((ks * 16 + (lane & 15)) * LDH) + jj * 16 + ((lane >> 4) << 3)) * 2u;
                    ldsm_x4_trans(r0, r1, r2, r3, addr);
                    mma_f16_16x8x16(O[2 * jj],     aP[ks], r0, r1);
                    mma_f16_16x8x16(O[2 * jj + 1], aP[ks], r2, r3);
                }
            }
        }
    }

    // ---- row-sum reduce + write ----
    l0 += __shfl_xor_sync(0xFFFFFFFFu, l0, 1);
    l0 += __shfl_xor_sync(0xFFFFFFFFu, l0, 2);
    l1 += __shfl_xor_sync(0xFFFFFFFFu, l1, 1);
    l1 += __shfl_xor_sync(0xFFFFFFFFu, l1, 2);
    {
        const float inv0 = 1.0f / l0;
        const float inv1 = 1.0f / l1;
        const int gr0 = q0 + w * 16 + g;
        __half* y0 = y + ((size_t)b * TT + gr0) * EE + h * DD;
        __half* y1 = y0 + 8 * EE;
        #pragma unroll
        for (int j = 0; j < 8; j++) {
            *(__half2*)&y0[j * 8 + 2 * t] = __floats2half2_rn(O[j][0] * inv0, O[j][1] * inv0);
            *(__half2*)&y1[j * 8 + 2 * t] = __floats2half2_rn(O[j][2] * inv1, O[j][3] * inv1);
        }
    }
}

// ---------------------------------------------------------------------------
// Launch
// ---------------------------------------------------------------------------
extern "C" void kernel_launch(void* const* d_in, const int* in_sizes, int n_in,
                              void* d_out, int out_size)
{
    const float* x      = (const float*)d_in[0];
    const float* W_qkv  = (const float*)d_in[1];
    const float* b_qkv  = (const float*)d_in[2];
    const float* W_proj = (const float*)d_in[3];
    const float* b_proj = (const float*)d_in[4];
    float* out = (float*)d_out;

    __half *qkvh, *yh, *xh, *wqh, *wph;
    cudaGetSymbolAddress((void**)&qkvh, g_qkvh);
    cudaGetSymbolAddress((void**)&yh, g_yh);
    cudaGetSymbolAddress((void**)&xh, g_xh);
    cudaGetSymbolAddress((void**)&wqh, g_wqh);
    cudaGetSymbolAddress((void**)&wph, g_wph);

    cudaFuncSetAttribute(gemm_f16<__half>, cudaFuncAttributeMaxDynamicSharedMemorySize, GSMEM_BYTES);
    cudaFuncSetAttribute(gemm_f16<float>,  cudaFuncAttributeMaxDynamicSharedMemorySize, GSMEM_BYTES);
    cudaFuncSetAttribute(attn_f16, cudaFuncAttributeMaxDynamicSharedMemorySize, ASMEM_BYTES);

    const int M = BATCH * TT;  // 8192

    // 0) fused fp32 -> fp16 conversions (one launch)
    {
        int n4x = (BATCH * TT * EE) / 4;
        int n4q = (EE * E3) / 4;
        int n4p = (EE * EE) / 4;
        int total = n4x + n4q + n4p;
        cvt_all_kernel<<<(total + 255) / 256, 256>>>(
            x, xh, n4x, W_qkv, wqh, n4q, W_proj, wph, n4p);
    }

    // 1) QKV projection (half output)
    {
        dim3 grid(E3 / 128, M / 128);
        gemm_f16<__half><<<grid, 128, GSMEM_BYTES>>>(xh, wqh, b_qkv, qkvh, M, E3, EE);
    }

    // 2) Attention (half output)
    {
        dim3 grid(TT / 128, BATCH * HH);
        attn_f16<<<grid, 256, ASMEM_BYTES>>>(qkvh, yh);
    }

    // 3) Output projection (fp32 output)
    {
        dim3 grid(EE / 128, M / 128);
        gemm_f16<float><<<grid, 128, GSMEM_BYTES>>>(yh, wph, b_proj, out, M, EE, EE);
    }
}

// round 16
// speedup vs baseline: 1.1027x; 1.1027x over previous
#include <cuda_runtime.h>
#include <cuda_fp16.h>
#include <mma.h>
#include <math.h>
#include <stdint.h>

using namespace nvcuda;

// Problem constants
#define BATCH 4
#define TT 2048
#define EE 1024
#define HH 16
#define DD 64
#define SEG 512
#define E3 3072

// Scratch (device globals: allocation-free)
static __device__ __half g_qkvh[(size_t)BATCH * TT * E3];
static __device__ __half g_yh[(size_t)BATCH * TT * EE];
static __device__ __half g_xh[(size_t)BATCH * TT * EE];
static __device__ __half g_wqh[(size_t)EE * E3];
static __device__ __half g_wph[(size_t)EE * EE];

// ---------------------------------------------------------------------------
// helpers
// ---------------------------------------------------------------------------
__device__ __forceinline__ void cp_async16(uint32_t smem_dst, const void* gsrc) {
    asm volatile("cp.async.cg.shared.global [%0], [%1], 16;\n" :: "r"(smem_dst), "l"(gsrc));
}
__device__ __forceinline__ void cp_commit() {
    asm volatile("cp.async.commit_group;\n" ::: "memory");
}
template <int N>
__device__ __forceinline__ void cp_wait() {
    asm volatile("cp.async.wait_group %0;\n" :: "n"(N) : "memory");
}
__device__ __forceinline__ void ldsm_x4(
    uint32_t& r0, uint32_t& r1, uint32_t& r2, uint32_t& r3, uint32_t addr)
{
    asm volatile("ldmatrix.sync.aligned.m8n8.x4.shared.b16 {%0,%1,%2,%3}, [%4];"
        : "=r"(r0), "=r"(r1), "=r"(r2), "=r"(r3) : "r"(addr));
}
__device__ __forceinline__ void ldsm_x4_trans(
    uint32_t& r0, uint32_t& r1, uint32_t& r2, uint32_t& r3, uint32_t addr)
{
    asm volatile("ldmatrix.sync.aligned.m8n8.x4.trans.shared.b16 {%0,%1,%2,%3}, [%4];"
        : "=r"(r0), "=r"(r1), "=r"(r2), "=r"(r3) : "r"(addr));
}
__device__ __forceinline__ float ex2f(float x) {
    float r;
    asm("ex2.approx.ftz.f32 %0, %1;" : "=f"(r) : "f"(x));
    return r;
}

// Fused fp32 -> fp16 conversion of x, W_qkv, W_proj in ONE launch.
__global__ __launch_bounds__(256) void cvt_all_kernel(
    const float* __restrict__ x,  __half* __restrict__ xh,  int n4x,
    const float* __restrict__ wq, __half* __restrict__ wqh, int n4q,
    const float* __restrict__ wp, __half* __restrict__ wph, int n4p)
{
    int i = blockIdx.x * 256 + threadIdx.x;
    const float* src; __half* dst; int off;
    if (i < n4x)                  { src = x;  dst = xh;  off = i; }
    else if (i < n4x + n4q)       { src = wq; dst = wqh; off = i - n4x; }
    else if (i < n4x + n4q + n4p) { src = wp; dst = wph; off = i - n4x - n4q; }
    else return;
    float4 v = ((const float4*)src)[off];
    ((__half2*)dst)[off * 2]     = __floats2half2_rn(v.x, v.y);
    ((__half2*)dst)[off * 2 + 1] = __floats2half2_rn(v.z, v.w);
}

// ---------------------------------------------------------------------------
// FP16 GEMM (exact R13/R14 passing config): C = A @ B + bias. 128x128 tile,
// BK=32, 4-stage cp.async ring, 4 warps (2x2), warp tile 64x64.
// ---------------------------------------------------------------------------
#define GLDA 40
#define GLDB 136
#define A_H (128 * GLDA)
#define B_H (32 * GLDB)
#define STAGE_H (A_H + B_H)
#define GSMEM_BYTES (4 * STAGE_H * 2)

template <typename OutT>
__global__ __launch_bounds__(128, 2) void gemm_f16(
    const __half* __restrict__ A, const __half* __restrict__ B,
    const float* __restrict__ bias, OutT* __restrict__ C,
    int M, int N, int K)
{
    extern __shared__ __half smemh[];
    const uint32_t smem_base = (uint32_t)__cvta_generic_to_shared(smemh);

    const int tid = threadIdx.x;
    const int wid = tid >> 5;
    const int wm = wid >> 1;
    const int wn = wid & 1;
    const int row0 = blockIdx.y * 128;
    const int col0 = blockIdx.x * 128;

    const int nsteps = K >> 5;

    auto stage_load = [&](int s, int k0) {
        uint32_t sa = smem_base + (uint32_t)(s * STAGE_H) * 2u;
        uint32_t sb = sa + (uint32_t)A_H * 2u;
        #pragma unroll
        for (int i = 0; i < 4; i++) {
            int c = tid + i * 128;
            int r = c >> 2, c8 = c & 3;
            cp_async16(sa + (uint32_t)(r * GLDA + c8 * 8) * 2u,
                       &A[(size_t)(row0 + r) * K + k0 + c8 * 8]);
        }
        #pragma unroll
        for (int i = 0; i < 4; i++) {
            int c = tid + i * 128;
            int r = c >> 4, c8 = c & 15;
            cp_async16(sb + (uint32_t)(r * GLDB + c8 * 8) * 2u,
                       &B[(size_t)(k0 + r) * N + col0 + c8 * 8]);
        }
    };

    wmma::fragment<wmma::accumulator, 16, 16, 16, float> acc[4][4];
    #pragma unroll
    for (int i = 0; i < 4; i++)
        #pragma unroll
        for (int j = 0; j < 4; j++)
            wmma::fill_fragment(acc[i][j], 0.0f);

    stage_load(0, 0);  cp_commit();
    stage_load(1, 32); cp_commit();
    stage_load(2, 64); cp_commit();

    for (int step = 0; step < nsteps; step++) {
        cp_wait<2>();
        __syncthreads();

        if (step + 3 < nsteps) stage_load((step + 3) & 3, (step + 3) * 32);
        cp_commit();

        const __half* sA = smemh + (step & 3) * STAGE_H;
        const __half* sB = sA + A_H;

        #pragma unroll
        for (int ks = 0; ks < 2; ks++) {
            wmma::fragment<wmma::matrix_a, 16, 16, 16, __half, wmma::row_major> af[4];
            wmma::fragment<wmma::matrix_b, 16, 16, 16, __half, wmma::row_major> bf[4];
            #pragma unroll
            for (int i = 0; i < 4; i++)
                wmma::load_matrix_sync(af[i], &sA[(wm * 64 + 16 * i) * GLDA + ks * 16], GLDA);
            #pragma unroll
            for (int j = 0; j < 4; j++)
                wmma::load_matrix_sync(bf[j], &sB[(ks * 16) * GLDB + wn * 64 + 16 * j], GLDB);
            #pragma unroll
            for (int i = 0; i < 4; i++)
                #pragma unroll
                for (int j = 0; j < 4; j++)
                    wmma::mma_sync(acc[i][j], af[i], bf[j], acc[i][j]);
        }
    }

    __syncthreads();

    // Epilogue via fp32 smem overlay
    float* sC = (float*)smemh;
    #pragma unroll
    for (int i = 0; i < 4; i++)
        #pragma unroll
        for (int j = 0; j < 4; j++)
            wmma::store_matrix_sync(&sC[(wm * 64 + 16 * i) * 132 + wn * 64 + 16 * j],
                                    acc[i][j], 132, wmma::mem_row_major);
    __syncthreads();

    #pragma unroll
    for (int idx = tid; idx < 4096; idx += 128) {
        int r = idx >> 5, c4 = idx & 31;
        float4 v = *(float4*)&sC[r * 132 + c4 * 4];
        float4 bv = *(const float4*)&bias[col0 + c4 * 4];
        v.x += bv.x; v.y += bv.y; v.z += bv.z; v.w += bv.w;
        if (sizeof(OutT) == 2) {
            __half2* dst = (__half2*)&C[(size_t)(row0 + r) * N + col0 + c4 * 4];
            dst[0] = __floats2half2_rn(v.x, v.y);
            dst[1] = __floats2half2_rn(v.z, v.w);
        } else {
            *(float4*)&((float*)C)[(size_t)(row0 + r) * N + col0 + c4 * 4] = v;
        }
    }
}

// ---------------------------------------------------------------------------
// Flash attention (R13 proven config + explicit 2-CTA residency):
// m16n8k16.f16 (fp32 acc), Br=128, Bc=64, 8 warps, 3-buffer 64-key KV ring,
// register-resident P, max-free softmax with scale*log2e folded into Q,
// K b-frags via ldmatrix.x4, V^T via ldmatrix.x4.trans.
// __launch_bounds__(256, 2): cap regs at 128 -> 2 CTAs/SM (smem 73.7KB x2 fits).
// ---------------------------------------------------------------------------
#define LDH 72
#define KV_TILE (64 * LDH)
#define ASMEM_BYTES ((6 * KV_TILE + 128 * LDH) * 2)   // 73728 B

__device__ __forceinline__ void mma_f16_16x8x16(
    float c[4], const uint32_t a[4], const uint32_t b0, const uint32_t b1)
{
    asm volatile(
        "mma.sync.aligned.m16n8k16.row.col.f32.f16.f16.f32 "
        "{%0,%1,%2,%3}, {%4,%5,%6,%7}, {%8,%9}, {%0,%1,%2,%3};"
        : "+f"(c[0]), "+f"(c[1]), "+f"(c[2]), "+f"(c[3])
        : "r"(a[0]), "r"(a[1]), "r"(a[2]), "r"(a[3]), "r"(b0), "r"(b1));
}

__global__ __launch_bounds__(256, 2) void attn_f16(
    const __half* __restrict__ qkv, __half* __restrict__ y)
{
    extern __shared__ __half smemh[];
    __half* sP = smemh + 6 * KV_TILE;   // Q staging only
    const uint32_t smem_u = (uint32_t)__cvta_generic_to_shared(smemh);
    const uint32_t sP_u = smem_u + (uint32_t)(6 * KV_TILE) * 2u;

    const int tid = threadIdx.x;
    const int w = tid >> 5;
    const int lane = tid & 31;
    const int g = lane >> 2;
    const int t = lane & 3;

    const int qt = (int)gridDim.x - 1 - (int)blockIdx.x;
    const int q0 = qt * 128;
    const int bh = blockIdx.y;
    const int b = bh / HH;
    const int h = bh % HH;

    const __half* base = qkv + (size_t)b * TT * E3 + h * DD;

    const bool causal = (q0 >= SEG);
    const int kv_end = causal ? (q0 + 128) : SEG;
    const int ntiles = kv_end >> 6;

    auto prefetch = [&](int tile) {
        const int s = tile % 3;
        uint32_t k_u = smem_u + (uint32_t)(s * KV_TILE) * 2u;
        uint32_t v_u = smem_u + (uint32_t)((3 + s) * KV_TILE) * 2u;
        const int kc0 = tile * 64;
        #pragma unroll
        for (int i = 0; i < 2; i++) {
            int idx = tid + i * 256;
            int r = idx >> 3, c8 = idx & 7;
            const __half* gp = &base[(size_t)(kc0 + r) * E3 + c8 * 8];
            uint32_t soff = (uint32_t)(r * LDH + c8 * 8) * 2u;
            cp_async16(k_u + soff, gp + EE);
            cp_async16(v_u + soff, gp + 2 * EE);
        }
    };

    #pragma unroll
    for (int i = 0; i < 4; i++) {
        int idx = tid + i * 256;
        int r = idx >> 3, c8 = idx & 7;
        cp_async16(sP_u + (uint32_t)(r * LDH + c8 * 8) * 2u,
                   &base[(size_t)(q0 + r) * E3 + c8 * 8]);
    }
    cp_commit();
    prefetch(0); cp_commit();
    prefetch(1); cp_commit();

    cp_wait<2>();
    __syncthreads();

    // Q a-frags, pre-scaled by scale*log2e = 0.18033688
    uint32_t aQ[4][4];
    {
        const int r0 = w * 16 + g;
        const __half2 qs = __float2half2_rn(0.18033688f);
        #pragma unroll
        for (int ks = 0; ks < 4; ks++) {
            __half2 v0 = *(const __half2*)&sP[r0 * LDH + ks * 16 + 2 * t];
            __half2 v1 = *(const __half2*)&sP[(r0 + 8) * LDH + ks * 16 + 2 * t];
            __half2 v2 = *(const __half2*)&sP[r0 * LDH + ks * 16 + 2 * t + 8];
            __half2 v3 = *(const __half2*)&sP[(r0 + 8) * LDH + ks * 16 + 2 * t + 8];
            v0 = __hmul2(v0, qs); v1 = __hmul2(v1, qs);
            v2 = __hmul2(v2, qs); v3 = __hmul2(v3, qs);
            aQ[ks][0] = *(uint32_t*)&v0;
            aQ[ks][1] = *(uint32_t*)&v1;
            aQ[ks][2] = *(uint32_t*)&v2;
            aQ[ks][3] = *(uint32_t*)&v3;
        }
    }

    float O[8][4];
    #pragma unroll
    for (int j = 0; j < 8; j++) { O[j][0] = O[j][1] = O[j][2] = O[j][3] = 0.0f; }
    float l0 = 0.0f, l1 = 0.0f;

    const int row0g = q0 + w * 16 + g;
    const int rowmax = q0 + w * 16 + 15;

    const int k_row_off = (lane & 7) + 8 * ((lane >> 4) & 1);
    const int k_col_off = ((lane >> 3) & 1) * 8;

    for (int tile = 0; tile < ntiles; tile++) {
        const int s = tile % 3;
        const int kc0 = tile * 64;

        cp_wait<1>();
        __syncthreads();

        if (tile + 2 < ntiles) prefetch(tile + 2);
        cp_commit();

        const uint32_t sK_u = smem_u + (uint32_t)(s * KV_TILE) * 2u;
        const uint32_t sV_u = smem_u + (uint32_t)((3 + s) * KV_TILE) * 2u;

        const bool active = !(causal && kc0 > rowmax);
        if (active) {
            // ---- S = (log2e*scale*Q) @ K^T ----
            float sacc[8][4];
            #pragma unroll
            for (int j = 0; j < 8; j++)
                sacc[j][0] = sacc[j][1] = sacc[j][2] = sacc[j][3] = 0.0f;
            #pragma unroll
            for (int ks = 0; ks < 4; ks++) {
                #pragma unroll
                for (int jp = 0; jp < 4; jp++) {
                    const int j = jp * 2;
                    uint32_t b0, b1, b2, b3;
                    uint32_t addr = sK_u +
                        (uint32_t)((j * 8 + k_row_off) * LDH + ks * 16 + k_col_off) * 2u;
                    ldsm_x4(b0, b1, b2, b3, addr);
                    mma_f16_16x8x16(sacc[j],     aQ[ks], b0, b1);
                    mma_f16_16x8x16(sacc[j + 1], aQ[ks], b2, b3);
                }
            }

            // ---- bare ex2 + pack P into a-frags ----
            const bool maskT = causal && (kc0 + 63 > q0 + w * 16);
            uint32_t aP[4][4];
            float sum0 = 0.0f, sum1 = 0.0f;
            #pragma unroll
            for (int j = 0; j < 8; j++) {
                float v0 = sacc[j][0];
                float v1 = sacc[j][1];
                float v2 = sacc[j][2];
                float v3 = sacc[j][3];
                if (maskT) {
                    int c = kc0 + j * 8 + 2 * t;
                    int r0m = row0g, r1m = row0g + 8;
                    if (c     > r0m) v0 = -1e30f;
                    if (c + 1 > r0m) v1 = -1e30f;
                    if (c     > r1m) v2 = -1e30f;
                    if (c + 1 > r1m) v3 = -1e30f;
                }
                float p0 = ex2f(v0);
                float p1 = ex2f(v1);
                float p2 = ex2f(v2);
                float p3 = ex2f(v3);
                sum0 += p0 + p1;
                sum1 += p2 + p3;
                __half2 h01 = __floats2half2_rn(p0, p1);
                __half2 h23 = __floats2half2_rn(p2, p3);
                const int ks = j >> 1;
                if ((j & 1) == 0) {
                    aP[ks][0] = *(uint32_t*)&h01;
                    aP[ks][1] = *(uint32_t*)&h23;
                } else {
                    aP[ks][2] = *(uint32_t*)&h01;
                    aP[ks][3] = *(uint32_t*)&h23;
                }
            }
            l0 += sum0;
            l1 += sum1;

            // ---- O += P @ V : V^T frags via ldmatrix.x4.trans ----
            #pragma unroll
            for (int ks = 0; ks < 4; ks++) {
                #pragma unroll
                for (int jj = 0; jj < 4; jj++) {
                    uint32_t r0, r1, r2, r3;
                    uint32_t addr = sV_u +
                        (uint32_t)(((ks * 16 + (lane & 15)) * LDH) + jj * 16 + ((lane >> 4) << 3)) * 2u;
                    ldsm_x4_trans(r0, r1, r2, r3, addr);
                    mma_f16_16x8x16(O[2 * jj],     aP[ks], r0, r1);
                    mma_f16_16x8x16(O[2 * jj + 1], aP[ks], r2, r3);
                }
            }
        }
    }

    // ---- row-sum reduce + write ----
    l0 += __shfl_xor_sync(0xFFFFFFFFu, l0, 1);
    l0 += __shfl_xor_sync(0xFFFFFFFFu, l0, 2);
    l1 += __shfl_xor_sync(0xFFFFFFFFu, l1, 1);
    l1 += __shfl_xor_sync(0xFFFFFFFFu, l1, 2);
    {
        const float inv0 = 1.0f / l0;
        const float inv1 = 1.0f / l1;
        const int gr0 = q0 + w * 16 + g;
        __half* y0 = y + ((size_t)b * TT + gr0) * EE + h * DD;
        __half* y1 = y0 + 8 * EE;
        #pragma unroll
        for (int j = 0; j < 8; j++) {
            *(__half2*)&y0[j * 8 + 2 * t] = __floats2half2_rn(O[j][0] * inv0, O[j][1] * inv0);
            *(__half2*)&y1[j * 8 + 2 * t] = __floats2half2_rn(O[j][2] * inv1, O[j][3] * inv1);
        }
    }
}

// ---------------------------------------------------------------------------
// Launch
// ---------------------------------------------------------------------------
extern "C" void kernel_launch(void* const* d_in, const int* in_sizes, int n_in,
                              void* d_out, int out_size)
{
    const float* x      = (const float*)d_in[0];
    const float* W_qkv  = (const float*)d_in[1];
    const float* b_qkv  = (const float*)d_in[2];
    const float* W_proj = (const float*)d_in[3];
    const float* b_proj = (const float*)d_in[4];
    float* out = (float*)d_out;

    __half *qkvh, *yh, *xh, *wqh, *wph;
    cudaGetSymbolAddress((void**)&qkvh, g_qkvh);
    cudaGetSymbolAddress((void**)&yh, g_yh);
    cudaGetSymbolAddress((void**)&xh, g_xh);
    cudaGetSymbolAddress((void**)&wqh, g_wqh);
    cudaGetSymbolAddress((void**)&wph, g_wph);

    cudaFuncSetAttribute(gemm_f16<__half>, cudaFuncAttributeMaxDynamicSharedMemorySize, GSMEM_BYTES);
    cudaFuncSetAttribute(gemm_f16<float>,  cudaFuncAttributeMaxDynamicSharedMemorySize, GSMEM_BYTES);
    cudaFuncSetAttribute(attn_f16, cudaFuncAttributeMaxDynamicSharedMemorySize, ASMEM_BYTES);

    const int M = BATCH * TT;  // 8192

    // 0) fused fp32 -> fp16 conversions (one launch)
    {
        int n4x = (BATCH * TT * EE) / 4;
        int n4q = (EE * E3) / 4;
        int n4p = (EE * EE) / 4;
        int total = n4x + n4q + n4p;
        cvt_all_kernel<<<(total + 255) / 256, 256>>>(
            x, xh, n4x, W_qkv, wqh, n4q, W_proj, wph, n4p);
    }

    // 1) QKV projection (half output)
    {
        dim3 grid(E3 / 128, M / 128);
        gemm_f16<__half><<<grid, 128, GSMEM_BYTES>>>(xh, wqh, b_qkv, qkvh, M, E3, EE);
    }

    // 2) Attention (half output)
    {
        dim3 grid(TT / 128, BATCH * HH);
        attn_f16<<<grid, 256, ASMEM_BYTES>>>(qkvh, yh);
    }

    // 3) Output projection (fp32 output)
    {
        dim3 grid(EE / 128, M / 128);
        gemm_f16<float><<<grid, 128, GSMEM_BYTES>>>(yh, wph, b_proj, out, M, EE, EE);
    }
}